// round 4
// baseline (speedup 1.0000x reference)
#include <cuda_runtime.h>
#include <cstdint>

#define N_NODES 50000
#define N_EDGES 600000
#define D 128

// Scratch (allocation-free rule: __device__ globals)
__device__ float g_h[(size_t)N_NODES * D];   // h = x @ W
__device__ float g_dis[N_NODES];             // rsqrt(deg)
__device__ int   g_idx_is32;                 // 1 if edge_index is int32, 0 if int64

// ---------------------------------------------------------------------------
// Index dtype probe: interpret first 128 words as int64; if any falls outside
// [0, N_NODES) the buffer must be int32 pairs. Deterministic (same input ->
// same result every launch).
// ---------------------------------------------------------------------------
__global__ void probe_kernel(const void* __restrict__ ei) {
    if (threadIdx.x == 0 && blockIdx.x == 0) {
        const long long* p = (const long long*)ei;
        int is32 = 0;
        for (int i = 0; i < 128; i++) {
            long long v = p[i];
            if (v < 0 || v >= N_NODES) { is32 = 1; break; }
        }
        g_idx_is32 = is32;
    }
}

__device__ __forceinline__ int load_idx(const void* ei, long long i, int is32) {
    if (is32) return ((const int*)ei)[i];
    return (int)((const long long*)ei)[i];
}

// ---------------------------------------------------------------------------
// Degree passes
// ---------------------------------------------------------------------------
__global__ void deg_init_kernel() {
    int i = blockIdx.x * blockDim.x + threadIdx.x;
    if (i < N_NODES) g_dis[i] = 1.0f;  // self-loop contributes 1 to every degree
}

__global__ void deg_count_kernel(const void* __restrict__ ei) {
    int e = blockIdx.x * blockDim.x + threadIdx.x;
    if (e < N_EDGES) {
        int is32 = g_idx_is32;
        int d = load_idx(ei, (long long)N_EDGES + e, is32);   // dst row
        atomicAdd(&g_dis[d], 1.0f);
    }
}

__global__ void deg_fin_kernel() {
    int i = blockIdx.x * blockDim.x + threadIdx.x;
    if (i < N_NODES) g_dis[i] = rsqrtf(g_dis[i]);  // deg >= 1 always (self loop)
}

// ---------------------------------------------------------------------------
// GEMM: h = x @ W, fused epilogue: out = b + h * dis^2  (self-loop + bias)
// Block: 256 threads (8 warps). Each block: 64 rows. Each warp: 8 rows.
// Lane l covers output cols [4l, 4l+4) via float4. W + X tile in smem.
// ---------------------------------------------------------------------------
__global__ void gemm_kernel(const float* __restrict__ x,
                            const float* __restrict__ W,
                            const float* __restrict__ b,
                            float* __restrict__ out) {
    extern __shared__ float smem[];
    float* Ws = smem;                 // 128*128 floats = 64 KB
    float* Xs = smem + D * D;         // 64*128 floats  = 32 KB

    const int tid  = threadIdx.x;
    const int row0 = blockIdx.x * 64;

    // Load W (coalesced, row-major [k][d])
    for (int i = tid; i < D * D; i += 256) Ws[i] = W[i];
    // Load X tile [64][128]
    for (int i = tid; i < 64 * D; i += 256) {
        int r = i >> 7, c = i & (D - 1);
        int gr = row0 + r;
        Xs[i] = (gr < N_NODES) ? x[(size_t)gr * D + c] : 0.0f;
    }
    __syncthreads();

    const int warp  = tid >> 5;
    const int lane  = tid & 31;
    const int c4    = lane * 4;
    const int rbase = warp * 8;

    float acc[8][4];
#pragma unroll
    for (int r = 0; r < 8; r++)
#pragma unroll
        for (int j = 0; j < 4; j++) acc[r][j] = 0.0f;

#pragma unroll 4
    for (int k = 0; k < D; k++) {
        float4 w = *(const float4*)&Ws[k * D + c4];   // LDS.128, conflict-free
#pragma unroll
        for (int r = 0; r < 8; r++) {
            float xv = Xs[(rbase + r) * D + k];        // broadcast
            acc[r][0] += xv * w.x;
            acc[r][1] += xv * w.y;
            acc[r][2] += xv * w.z;
            acc[r][3] += xv * w.w;
        }
    }

    float4 bv = *(const float4*)&b[c4];
#pragma unroll
    for (int r = 0; r < 8; r++) {
        int gr = row0 + rbase + r;
        if (gr < N_NODES) {
            float di = g_dis[gr];
            float sl = di * di;  // self-loop norm
            float4 hv = make_float4(acc[r][0], acc[r][1], acc[r][2], acc[r][3]);
            *(float4*)&g_h[(size_t)gr * D + c4] = hv;
            float4 ov;
            ov.x = bv.x + hv.x * sl;
            ov.y = bv.y + hv.y * sl;
            ov.z = bv.z + hv.z * sl;
            ov.w = bv.w + hv.w * sl;
            *(float4*)&out[(size_t)gr * D + c4] = ov;
        }
    }
}

// ---------------------------------------------------------------------------
// Edge scatter: one warp per edge, lane l handles 4 floats.
// out[dst] += h[src] * (dis[src]*dis[dst]) via vector f32 reduction (sm_90+).
// ---------------------------------------------------------------------------
__global__ void scatter_kernel(const void* __restrict__ ei,
                               float* __restrict__ out) {
    int e = blockIdx.x * (blockDim.x >> 5) + (threadIdx.x >> 5);
    int lane = threadIdx.x & 31;
    if (e >= N_EDGES) return;

    int is32 = g_idx_is32;
    int s = load_idx(ei, e, is32);
    int d = load_idx(ei, (long long)N_EDGES + e, is32);
    float norm = g_dis[s] * g_dis[d];

    const float4* hp = (const float4*)(g_h + (size_t)s * D);
    float4 v = hp[lane];
    v.x *= norm; v.y *= norm; v.z *= norm; v.w *= norm;

    float* addr = out + (size_t)d * D + lane * 4;
    asm volatile("red.global.add.v4.f32 [%0], {%1, %2, %3, %4};"
                 :: "l"(addr), "f"(v.x), "f"(v.y), "f"(v.z), "f"(v.w)
                 : "memory");
}

// ---------------------------------------------------------------------------
// Launch
// ---------------------------------------------------------------------------
extern "C" void kernel_launch(void* const* d_in, const int* in_sizes, int n_in,
                              void* d_out, int out_size) {
    const float* x  = (const float*)d_in[0];
    const void*  ei = d_in[1];                 // [2, E], int32 or int64 (probed)
    const float* W  = (const float*)d_in[2];
    const float* b  = (const float*)d_in[3];
    float*       out = (float*)d_out;

    // Detect index dtype (deterministic, graph-capturable)
    probe_kernel<<<1, 32>>>(ei);

    // Degree
    deg_init_kernel<<<(N_NODES + 255) / 256, 256>>>();
    deg_count_kernel<<<(N_EDGES + 255) / 256, 256>>>(ei);
    deg_fin_kernel<<<(N_NODES + 255) / 256, 256>>>();

    // GEMM + self-loop/bias epilogue (also fully initializes d_out)
    const int smem_bytes = (D * D + 64 * D) * sizeof(float);  // 96 KB
    cudaFuncSetAttribute(gemm_kernel,
                         cudaFuncAttributeMaxDynamicSharedMemorySize, smem_bytes);
    gemm_kernel<<<(N_NODES + 63) / 64, 256, smem_bytes>>>(x, W, b, out);

    // Edge scatter-add
    const int warps_per_block = 8;  // 256 threads
    int blocks = (N_EDGES + warps_per_block - 1) / warps_per_block;
    scatter_kernel<<<blocks, 256>>>(ei, out);
}

// round 7
// speedup vs baseline: 1.0829x; 1.0829x over previous
#include <cuda_runtime.h>
#include <cuda_bf16.h>
#include <cstdint>

#define N_NODES 50000
#define N_EDGES 600000
#define D 128

// ---------------------------------------------------------------------------
// Scratch (__device__ globals; zero-initialized at module load)
// ---------------------------------------------------------------------------
__device__ float g_h[(size_t)N_NODES * D];   // h = x @ W
__device__ float g_dis[N_NODES];             // rsqrt(deg+1)
__device__ int   g_deg[N_NODES];             // in-degree counts (reset by gemm)
__device__ int   g_idx_is32;                 // 1 if edge_index is int32

// ---------------------------------------------------------------------------
// Index dtype handling
// ---------------------------------------------------------------------------
__device__ __forceinline__ int probe_is32(const void* ei) {
    const long long* p = (const long long*)ei;
    int is32 = 0;
#pragma unroll
    for (int i = 0; i < 4; i++) {
        long long v = p[i];
        if (v < 0 || v >= N_NODES) is32 = 1;
    }
    return is32;
}
__device__ __forceinline__ int load_idx(const void* ei, long long i, int is32) {
    if (is32) return ((const int*)ei)[i];
    return (int)((const long long*)ei)[i];
}

// ---------------------------------------------------------------------------
// K1: degree count (+ publish index dtype)
// ---------------------------------------------------------------------------
__global__ void deg_count_kernel(const void* __restrict__ ei) {
    int e = blockIdx.x * blockDim.x + threadIdx.x;
    int is32 = probe_is32(ei);
    if (e == 0) g_idx_is32 = is32;
    if (e < N_EDGES) {
        int d = load_idx(ei, (long long)N_EDGES + e, is32);
        atomicAdd(&g_deg[d], 1);
    }
}

// ---------------------------------------------------------------------------
// K2: bf16-3x tensor GEMM via mma.sync.m16n8k16 (base PTX, HMMA).
// Block: 256 threads (8 warps), 128 rows. Warp w computes rows [16w,16w+16)
// x all 128 cols (16 n-tiles of 8). K=128 in 8 steps of 16.
// D = Ahi*Bhi + Ahi*Blo + Alo*Bhi, fp32 accum  (error ~2^-17).
// Fused: g_dis = rsqrt(g_deg+1), g_deg reset, out = b + h*dis^2 (self-loop).
//
// SMEM rows are 128 bf16 of data padded to 136 bf16 (68 words). Fragment
// load addr = row*68 + ks*8 + t  ->  bank = 4g+t  (conflict-free).
// ---------------------------------------------------------------------------
#define APAD      136         // bf16 per padded row (128 data + 8 pad)
#define APADW     68          // words per padded row
#define TILE_B    (128 * APAD * 2)   // 34816 bytes per tile
#define SM_DIS    0                   // float[128]
#define SM_AHI    512
#define SM_ALO    (SM_AHI + TILE_B)
#define SM_BHI    (SM_ALO + TILE_B)
#define SM_BLO    (SM_BHI + TILE_B)
#define SM_TOTAL  (SM_BLO + TILE_B)  // 139776 bytes

__device__ __forceinline__ void mma16816(float* c, const uint32_t* a,
                                         uint32_t b0, uint32_t b1) {
    asm volatile(
        "mma.sync.aligned.m16n8k16.row.col.f32.bf16.bf16.f32 "
        "{%0,%1,%2,%3}, {%4,%5,%6,%7}, {%8,%9}, {%0,%1,%2,%3};"
        : "+f"(c[0]), "+f"(c[1]), "+f"(c[2]), "+f"(c[3])
        : "r"(a[0]), "r"(a[1]), "r"(a[2]), "r"(a[3]), "r"(b0), "r"(b1));
}

__device__ __forceinline__ uint32_t pack_hi2(float x, float y) {
    __nv_bfloat162 t = make_bfloat162(__float2bfloat16_rn(x), __float2bfloat16_rn(y));
    return *(uint32_t*)&t;
}
__device__ __forceinline__ uint32_t pack_lo2(float x, float y) {
    float hx = __bfloat162float(__float2bfloat16_rn(x));
    float hy = __bfloat162float(__float2bfloat16_rn(y));
    __nv_bfloat162 t = make_bfloat162(__float2bfloat16_rn(x - hx),
                                      __float2bfloat16_rn(y - hy));
    return *(uint32_t*)&t;
}

__global__ void __launch_bounds__(256, 1)
gemm_kernel(const float* __restrict__ x,
            const float* __restrict__ W,
            const float* __restrict__ bias,
            float* __restrict__ out) {
    extern __shared__ char smem[];
    float*    ep_dis = (float*)(smem + SM_DIS);
    uint32_t* AsHi = (uint32_t*)(smem + SM_AHI);
    uint32_t* AsLo = (uint32_t*)(smem + SM_ALO);
    uint32_t* BsHi = (uint32_t*)(smem + SM_BHI);
    uint32_t* BsLo = (uint32_t*)(smem + SM_BLO);

    const int tid  = threadIdx.x;
    const int wid  = tid >> 5;
    const int lane = tid & 31;
    const int row0 = blockIdx.x * 128;

    // --- Degree finalize for this block's rows (feeds epilogue + scatter) ---
    if (tid < 128) {
        int gr = row0 + tid;
        float dis = 0.0f;
        if (gr < N_NODES) {
            int deg = g_deg[gr];
            dis = rsqrtf((float)(deg + 1));
            g_dis[gr] = dis;
            g_deg[gr] = 0;           // reset for next graph replay
        }
        ep_dis[tid] = dis;
    }

    // --- A tile: x[row0..row0+128) -> hi/lo bf16 ---
    for (int i = tid; i < 128 * 32; i += 256) {
        int r  = i >> 5;
        int c4 = (i & 31) << 2;
        int gr = row0 + r;
        float4 v = make_float4(0.f, 0.f, 0.f, 0.f);
        if (gr < N_NODES) v = *(const float4*)(x + (size_t)gr * D + c4);
        uint32_t* dh = AsHi + r * APADW + (c4 >> 1);
        uint32_t* dl = AsLo + r * APADW + (c4 >> 1);
        dh[0] = pack_hi2(v.x, v.y);
        dh[1] = pack_hi2(v.z, v.w);
        dl[0] = pack_lo2(v.x, v.y);
        dl[1] = pack_lo2(v.z, v.w);
    }

    // --- B tile: W^T (n-major rows, k contiguous) hi/lo bf16 ---
    for (int i = tid; i < 128 * 64; i += 256) {
        int k  = i >> 6;            // W row
        int n2 = (i & 63) << 1;     // W col pair
        float2 v = *(const float2*)(W + k * D + n2);
        __nv_bfloat16* bh = (__nv_bfloat16*)(smem + SM_BHI);
        __nv_bfloat16* bl = (__nv_bfloat16*)(smem + SM_BLO);
        float h0f = __bfloat162float(__float2bfloat16_rn(v.x));
        float h1f = __bfloat162float(__float2bfloat16_rn(v.y));
        bh[(n2 + 0) * APAD + k] = __float2bfloat16_rn(v.x);
        bh[(n2 + 1) * APAD + k] = __float2bfloat16_rn(v.y);
        bl[(n2 + 0) * APAD + k] = __float2bfloat16_rn(v.x - h0f);
        bl[(n2 + 1) * APAD + k] = __float2bfloat16_rn(v.y - h1f);
    }
    __syncthreads();

    // --- MMA mainloop ---
    const int g = lane >> 2;        // group id (0..7)
    const int t = lane & 3;         // thread-in-group (0..3)
    const int wrow = wid * 16;

    float acc[16][4];
#pragma unroll
    for (int nt = 0; nt < 16; nt++)
#pragma unroll
        for (int j = 0; j < 4; j++) acc[nt][j] = 0.0f;

#pragma unroll
    for (int ks = 0; ks < 8; ks++) {
        const int kw = ks * 8 + t;  // word index within padded row
        uint32_t ahi[4], alo[4];
        ahi[0] = AsHi[(wrow + g)     * APADW + kw];
        ahi[1] = AsHi[(wrow + g + 8) * APADW + kw];
        ahi[2] = AsHi[(wrow + g)     * APADW + kw + 4];
        ahi[3] = AsHi[(wrow + g + 8) * APADW + kw + 4];
        alo[0] = AsLo[(wrow + g)     * APADW + kw];
        alo[1] = AsLo[(wrow + g + 8) * APADW + kw];
        alo[2] = AsLo[(wrow + g)     * APADW + kw + 4];
        alo[3] = AsLo[(wrow + g + 8) * APADW + kw + 4];
#pragma unroll
        for (int nt = 0; nt < 16; nt++) {
            const int brow = (nt * 8 + g) * APADW + kw;
            uint32_t bh0 = BsHi[brow], bh1 = BsHi[brow + 4];
            uint32_t bl0 = BsLo[brow], bl1 = BsLo[brow + 4];
            mma16816(acc[nt], ahi, bh0, bh1);
            mma16816(acc[nt], ahi, bl0, bl1);
            mma16816(acc[nt], alo, bh0, bh1);
        }
    }

    // --- Epilogue: direct global stores ---
    const int r0 = row0 + wrow + g;
    const int r1 = r0 + 8;
    const float d0 = ep_dis[wrow + g];
    const float d1 = ep_dis[wrow + g + 8];
    const float sl0 = d0 * d0, sl1 = d1 * d1;
    const bool ok0 = (r0 < N_NODES), ok1 = (r1 < N_NODES);
#pragma unroll
    for (int nt = 0; nt < 16; nt++) {
        const int c = nt * 8 + 2 * t;
        float2 bv = *(const float2*)(bias + c);
        if (ok0) {
            float2 hv = make_float2(acc[nt][0], acc[nt][1]);
            *(float2*)(g_h + (size_t)r0 * D + c) = hv;
            *(float2*)(out + (size_t)r0 * D + c) =
                make_float2(bv.x + hv.x * sl0, bv.y + hv.y * sl0);
        }
        if (ok1) {
            float2 hv = make_float2(acc[nt][2], acc[nt][3]);
            *(float2*)(g_h + (size_t)r1 * D + c) = hv;
            *(float2*)(out + (size_t)r1 * D + c) =
                make_float2(bv.x + hv.x * sl1, bv.y + hv.y * sl1);
        }
    }
}

// ---------------------------------------------------------------------------
// K3: edge scatter. One warp per edge; lane l handles 4 floats.
// out[dst] += h[src] * (dis[src]*dis[dst]) via red.global.add.v4.f32
// ---------------------------------------------------------------------------
__global__ void scatter_kernel(const void* __restrict__ ei,
                               float* __restrict__ out) {
    int e = blockIdx.x * (blockDim.x >> 5) + (threadIdx.x >> 5);
    int lane = threadIdx.x & 31;
    if (e >= N_EDGES) return;

    int is32 = g_idx_is32;
    int s = load_idx(ei, e, is32);
    int d = load_idx(ei, (long long)N_EDGES + e, is32);
    float norm = g_dis[s] * g_dis[d];

    float4 v = ((const float4*)(g_h + (size_t)s * D))[lane];
    v.x *= norm; v.y *= norm; v.z *= norm; v.w *= norm;

    float* addr = out + (size_t)d * D + lane * 4;
    asm volatile("red.global.add.v4.f32 [%0], {%1, %2, %3, %4};"
                 :: "l"(addr), "f"(v.x), "f"(v.y), "f"(v.z), "f"(v.w)
                 : "memory");
}

// ---------------------------------------------------------------------------
// Launch: 3 kernels
// ---------------------------------------------------------------------------
extern "C" void kernel_launch(void* const* d_in, const int* in_sizes, int n_in,
                              void* d_out, int out_size) {
    const float* x  = (const float*)d_in[0];
    const void*  ei = d_in[1];                 // [2, E], int32 or int64 (probed)
    const float* W  = (const float*)d_in[2];
    const float* b  = (const float*)d_in[3];
    float*       out = (float*)d_out;

    deg_count_kernel<<<(N_EDGES + 255) / 256, 256>>>(ei);

    cudaFuncSetAttribute(gemm_kernel,
                         cudaFuncAttributeMaxDynamicSharedMemorySize, SM_TOTAL);
    gemm_kernel<<<(N_NODES + 127) / 128, 256, SM_TOTAL>>>(x, W, b, out);

    const int warps_per_block = 8;  // 256 threads
    int blocks = (N_EDGES + warps_per_block - 1) / warps_per_block;
    scatter_kernel<<<blocks, 256>>>(ei, out);
}

// round 9
// speedup vs baseline: 1.2230x; 1.1294x over previous
#include <cuda_runtime.h>
#include <cuda_bf16.h>
#include <cuda_fp16.h>
#include <cstdint>

#define N_NODES 50000
#define N_EDGES 600000
#define D 128

// ---------------------------------------------------------------------------
// Scratch (__device__ globals; zero-initialized at module load)
// ---------------------------------------------------------------------------
__device__ __half g_h16[(size_t)N_NODES * D]; // h = x @ W   (fp16, 12.8 MB)
__device__ float  g_dis[N_NODES];             // rsqrt(deg+1)
__device__ int    g_deg[N_NODES];             // in-degree counts (reset by gemm)
__device__ int    g_idx_is32;                 // 1 if edge_index is int32

// ---------------------------------------------------------------------------
// Index dtype handling
// ---------------------------------------------------------------------------
__device__ __forceinline__ int probe_is32(const void* ei) {
    const long long* p = (const long long*)ei;
    int is32 = 0;
#pragma unroll
    for (int i = 0; i < 4; i++) {
        long long v = p[i];
        if (v < 0 || v >= N_NODES) is32 = 1;
    }
    return is32;
}
__device__ __forceinline__ int load_idx(const void* ei, long long i, int is32) {
    if (is32) return ((const int*)ei)[i];
    return (int)((const long long*)ei)[i];
}

// ---------------------------------------------------------------------------
// K1: degree count, 2 edges per thread (+ publish index dtype)
// ---------------------------------------------------------------------------
__global__ void deg_count_kernel(const void* __restrict__ ei) {
    int e0 = (blockIdx.x * blockDim.x + threadIdx.x) * 2;
    int is32 = probe_is32(ei);
    if (e0 == 0) g_idx_is32 = is32;
#pragma unroll
    for (int j = 0; j < 2; j++) {
        int e = e0 + j;
        if (e < N_EDGES) {
            int d = load_idx(ei, (long long)N_EDGES + e, is32);
            atomicAdd(&g_deg[d], 1);
        }
    }
}

// ---------------------------------------------------------------------------
// K2: bf16-3x tensor GEMM via mma.sync.m16n8k16 (base PTX, HMMA).
// Block: 256 threads (8 warps), 128 rows. Warp w computes rows [16w,16w+16)
// x all 128 cols (16 n-tiles of 8). K=128 in 8 steps of 16.
// D = Ahi*Bhi + Ahi*Blo + Alo*Bhi, fp32 accum  (error ~2^-17).
// Fused: g_dis = rsqrt(g_deg+1), g_deg reset, out = b + h*dis^2 (self-loop),
// g_h16 = fp16(h) for the edge scatter.
//
// SMEM rows: 128 bf16 data padded to 136 (68 words). Fragment load addr =
// row*68 + ks*8 + t  ->  bank = 4g+t  (conflict-free).
// ---------------------------------------------------------------------------
#define APAD      136
#define APADW     68
#define TILE_B    (128 * APAD * 2)
#define SM_DIS    0
#define SM_AHI    512
#define SM_ALO    (SM_AHI + TILE_B)
#define SM_BHI    (SM_ALO + TILE_B)
#define SM_BLO    (SM_BHI + TILE_B)
#define SM_TOTAL  (SM_BLO + TILE_B)  // 139776 bytes

__device__ __forceinline__ void mma16816(float* c, const uint32_t* a,
                                         uint32_t b0, uint32_t b1) {
    asm volatile(
        "mma.sync.aligned.m16n8k16.row.col.f32.bf16.bf16.f32 "
        "{%0,%1,%2,%3}, {%4,%5,%6,%7}, {%8,%9}, {%0,%1,%2,%3};"
        : "+f"(c[0]), "+f"(c[1]), "+f"(c[2]), "+f"(c[3])
        : "r"(a[0]), "r"(a[1]), "r"(a[2]), "r"(a[3]), "r"(b0), "r"(b1));
}

__device__ __forceinline__ uint32_t pack_hi2(float x, float y) {
    __nv_bfloat162 t = make_bfloat162(__float2bfloat16_rn(x), __float2bfloat16_rn(y));
    return *(uint32_t*)&t;
}
__device__ __forceinline__ uint32_t pack_lo2(float x, float y) {
    float hx = __bfloat162float(__float2bfloat16_rn(x));
    float hy = __bfloat162float(__float2bfloat16_rn(y));
    __nv_bfloat162 t = make_bfloat162(__float2bfloat16_rn(x - hx),
                                      __float2bfloat16_rn(y - hy));
    return *(uint32_t*)&t;
}

__global__ void __launch_bounds__(256, 1)
gemm_kernel(const float* __restrict__ x,
            const float* __restrict__ W,
            const float* __restrict__ bias,
            float* __restrict__ out) {
    extern __shared__ char smem[];
    float*    ep_dis = (float*)(smem + SM_DIS);
    uint32_t* AsHi = (uint32_t*)(smem + SM_AHI);
    uint32_t* AsLo = (uint32_t*)(smem + SM_ALO);
    uint32_t* BsHi = (uint32_t*)(smem + SM_BHI);
    uint32_t* BsLo = (uint32_t*)(smem + SM_BLO);

    const int tid  = threadIdx.x;
    const int wid  = tid >> 5;
    const int lane = tid & 31;
    const int row0 = blockIdx.x * 128;

    // --- Degree finalize for this block's rows ---
    if (tid < 128) {
        int gr = row0 + tid;
        float dis = 0.0f;
        if (gr < N_NODES) {
            int deg = g_deg[gr];
            dis = rsqrtf((float)(deg + 1));
            g_dis[gr] = dis;
            g_deg[gr] = 0;           // reset for next graph replay
        }
        ep_dis[tid] = dis;
    }

    // --- A tile: x[row0..row0+128) -> hi/lo bf16 ---
    for (int i = tid; i < 128 * 32; i += 256) {
        int r  = i >> 5;
        int c4 = (i & 31) << 2;
        int gr = row0 + r;
        float4 v = make_float4(0.f, 0.f, 0.f, 0.f);
        if (gr < N_NODES) v = *(const float4*)(x + (size_t)gr * D + c4);
        uint32_t* dh = AsHi + r * APADW + (c4 >> 1);
        uint32_t* dl = AsLo + r * APADW + (c4 >> 1);
        dh[0] = pack_hi2(v.x, v.y);
        dh[1] = pack_hi2(v.z, v.w);
        dl[0] = pack_lo2(v.x, v.y);
        dl[1] = pack_lo2(v.z, v.w);
    }

    // --- B tile: W^T (n-major rows, k contiguous) hi/lo bf16 ---
    for (int i = tid; i < 128 * 64; i += 256) {
        int k  = i >> 6;
        int n2 = (i & 63) << 1;
        float2 v = *(const float2*)(W + k * D + n2);
        __nv_bfloat16* bh = (__nv_bfloat16*)(smem + SM_BHI);
        __nv_bfloat16* bl = (__nv_bfloat16*)(smem + SM_BLO);
        float h0f = __bfloat162float(__float2bfloat16_rn(v.x));
        float h1f = __bfloat162float(__float2bfloat16_rn(v.y));
        bh[(n2 + 0) * APAD + k] = __float2bfloat16_rn(v.x);
        bh[(n2 + 1) * APAD + k] = __float2bfloat16_rn(v.y);
        bl[(n2 + 0) * APAD + k] = __float2bfloat16_rn(v.x - h0f);
        bl[(n2 + 1) * APAD + k] = __float2bfloat16_rn(v.y - h1f);
    }
    __syncthreads();

    // --- MMA mainloop ---
    const int g = lane >> 2;
    const int t = lane & 3;
    const int wrow = wid * 16;

    float acc[16][4];
#pragma unroll
    for (int nt = 0; nt < 16; nt++)
#pragma unroll
        for (int j = 0; j < 4; j++) acc[nt][j] = 0.0f;

#pragma unroll
    for (int ks = 0; ks < 8; ks++) {
        const int kw = ks * 8 + t;
        uint32_t ahi[4], alo[4];
        ahi[0] = AsHi[(wrow + g)     * APADW + kw];
        ahi[1] = AsHi[(wrow + g + 8) * APADW + kw];
        ahi[2] = AsHi[(wrow + g)     * APADW + kw + 4];
        ahi[3] = AsHi[(wrow + g + 8) * APADW + kw + 4];
        alo[0] = AsLo[(wrow + g)     * APADW + kw];
        alo[1] = AsLo[(wrow + g + 8) * APADW + kw];
        alo[2] = AsLo[(wrow + g)     * APADW + kw + 4];
        alo[3] = AsLo[(wrow + g + 8) * APADW + kw + 4];
#pragma unroll
        for (int nt = 0; nt < 16; nt++) {
            const int brow = (nt * 8 + g) * APADW + kw;
            uint32_t bh0 = BsHi[brow], bh1 = BsHi[brow + 4];
            uint32_t bl0 = BsLo[brow], bl1 = BsLo[brow + 4];
            mma16816(acc[nt], ahi, bh0, bh1);
            mma16816(acc[nt], ahi, bl0, bl1);
            mma16816(acc[nt], alo, bh0, bh1);
        }
    }

    // --- Epilogue: fp32 out (bias + self-loop) + fp16 h for scatter ---
    const int r0 = row0 + wrow + g;
    const int r1 = r0 + 8;
    const float d0 = ep_dis[wrow + g];
    const float d1 = ep_dis[wrow + g + 8];
    const float sl0 = d0 * d0, sl1 = d1 * d1;
    const bool ok0 = (r0 < N_NODES), ok1 = (r1 < N_NODES);
#pragma unroll
    for (int nt = 0; nt < 16; nt++) {
        const int c = nt * 8 + 2 * t;
        float2 bv = *(const float2*)(bias + c);
        if (ok0) {
            float2 hv = make_float2(acc[nt][0], acc[nt][1]);
            *(__half2*)(g_h16 + (size_t)r0 * D + c) = __float22half2_rn(hv);
            *(float2*)(out + (size_t)r0 * D + c) =
                make_float2(bv.x + hv.x * sl0, bv.y + hv.y * sl0);
        }
        if (ok1) {
            float2 hv = make_float2(acc[nt][2], acc[nt][3]);
            *(__half2*)(g_h16 + (size_t)r1 * D + c) = __float22half2_rn(hv);
            *(float2*)(out + (size_t)r1 * D + c) =
                make_float2(bv.x + hv.x * sl1, bv.y + hv.y * sl1);
        }
    }
}

// ---------------------------------------------------------------------------
// K3: edge scatter. 4 edges per warp; lane l handles 4 cols.
// Gather fp16 h[src] (8B/lane, 256B/warp coalesced), scale, reduce fp32.
// ---------------------------------------------------------------------------
#define EPW 4
__global__ void scatter_kernel(const void* __restrict__ ei,
                               float* __restrict__ out) {
    int warp_g = blockIdx.x * (blockDim.x >> 5) + (threadIdx.x >> 5);
    int lane = threadIdx.x & 31;
    long long e0 = (long long)warp_g * EPW;
    if (e0 >= N_EDGES) return;
    int is32 = g_idx_is32;

#pragma unroll
    for (int j = 0; j < EPW; j++) {
        long long e = e0 + j;
        if (e >= N_EDGES) break;
        int s = load_idx(ei, e, is32);
        int d = load_idx(ei, (long long)N_EDGES + e, is32);
        float norm = g_dis[s] * g_dis[d];

        uint2 u = ((const uint2*)(g_h16 + (size_t)s * D))[lane];
        float2 f0 = __half22float2(*(__half2*)&u.x);
        float2 f1 = __half22float2(*(__half2*)&u.y);

        float* addr = out + (size_t)d * D + lane * 4;
        asm volatile("red.global.add.v4.f32 [%0], {%1, %2, %3, %4};"
                     :: "l"(addr), "f"(f0.x * norm), "f"(f0.y * norm),
                        "f"(f1.x * norm), "f"(f1.y * norm)
                     : "memory");
    }
}

// ---------------------------------------------------------------------------
// Launch: 3 kernels
// ---------------------------------------------------------------------------
extern "C" void kernel_launch(void* const* d_in, const int* in_sizes, int n_in,
                              void* d_out, int out_size) {
    const float* x  = (const float*)d_in[0];
    const void*  ei = d_in[1];
    const float* W  = (const float*)d_in[2];
    const float* b  = (const float*)d_in[3];
    float*       out = (float*)d_out;

    deg_count_kernel<<<(N_EDGES + 511) / 512, 256>>>(ei);

    cudaFuncSetAttribute(gemm_kernel,
                         cudaFuncAttributeMaxDynamicSharedMemorySize, SM_TOTAL);
    gemm_kernel<<<(N_NODES + 127) / 128, 256, SM_TOTAL>>>(x, W, b, out);

    // 8 warps/block, 4 edges/warp -> 32 edges/block
    int blocks = (N_EDGES + 32 - 1) / 32;
    scatter_kernel<<<blocks, 256>>>(ei, out);
}

// round 10
// speedup vs baseline: 1.5658x; 1.2803x over previous
#include <cuda_runtime.h>
#include <cuda_bf16.h>
#include <cuda_fp16.h>
#include <cstdint>

#define N_NODES 50000
#define N_EDGES 600000
#define D 128
#define SCAN_BLK 512
#define N_SBLK ((N_NODES + SCAN_BLK - 1) / SCAN_BLK)   // 98

// ---------------------------------------------------------------------------
// Scratch (__device__ globals; zero-initialized at module load)
// ---------------------------------------------------------------------------
__device__ __half g_h16[(size_t)N_NODES * D]; // h~ = fp16(h * dis[src])
__device__ float  g_dis[N_NODES];             // rsqrt(deg+1)
__device__ int    g_deg[N_NODES];             // in-degree counts (reset by gemm)
__device__ int    g_idx_is32;                 // 1 if edge_index is int32
__device__ int    g_esrc[N_EDGES];            // CSR: src ids grouped by dst
__device__ int    g_rowstart[N_NODES + 1];    // CSR row offsets
__device__ int    g_cursor[N_NODES];          // fill cursors (rebuilt per replay)
__device__ int    g_bsum[128];                // scan block sums

// ---------------------------------------------------------------------------
// Index dtype handling
// ---------------------------------------------------------------------------
__device__ __forceinline__ int probe_is32(const void* ei) {
    const long long* p = (const long long*)ei;
    int is32 = 0;
#pragma unroll
    for (int i = 0; i < 4; i++) {
        long long v = p[i];
        if (v < 0 || v >= N_NODES) is32 = 1;
    }
    return is32;
}
__device__ __forceinline__ int load_idx(const void* ei, long long i, int is32) {
    if (is32) return ((const int*)ei)[i];
    return (int)((const long long*)ei)[i];
}

// ---------------------------------------------------------------------------
// K1: degree count, 2 edges per thread (+ publish index dtype)
// ---------------------------------------------------------------------------
__global__ void deg_count_kernel(const void* __restrict__ ei) {
    int e0 = (blockIdx.x * blockDim.x + threadIdx.x) * 2;
    int is32 = probe_is32(ei);
    if (e0 == 0) g_idx_is32 = is32;
#pragma unroll
    for (int j = 0; j < 2; j++) {
        int e = e0 + j;
        if (e < N_EDGES) {
            int d = load_idx(ei, (long long)N_EDGES + e, is32);
            atomicAdd(&g_deg[d], 1);
        }
    }
}

// ---------------------------------------------------------------------------
// K2a/b/c: exclusive scan of g_deg -> g_rowstart, g_cursor
// ---------------------------------------------------------------------------
__global__ void scan1_kernel() {            // per-block sums
    __shared__ int red[16];
    int i = blockIdx.x * SCAN_BLK + threadIdx.x;
    int v = (i < N_NODES) ? g_deg[i] : 0;
#pragma unroll
    for (int o = 16; o; o >>= 1) v += __shfl_down_sync(0xffffffffu, v, o);
    if ((threadIdx.x & 31) == 0) red[threadIdx.x >> 5] = v;
    __syncthreads();
    if (threadIdx.x == 0) {
        int s = 0;
#pragma unroll
        for (int j = 0; j < 16; j++) s += red[j];
        g_bsum[blockIdx.x] = s;
    }
}

__global__ void scan2_kernel() {            // scan the 98 block sums (1 block, 128 thr)
    int t = threadIdx.x;
    int lane = t & 31, w = t >> 5;
    int v = (t < N_SBLK) ? g_bsum[t] : 0;
    int x = v;
#pragma unroll
    for (int o = 1; o < 32; o <<= 1) {
        int y = __shfl_up_sync(0xffffffffu, x, o);
        if (lane >= o) x += y;
    }
    __shared__ int ws[4];
    if (lane == 31) ws[w] = x;
    __syncthreads();
    int off = 0;
    for (int j = 0; j < w; j++) off += ws[j];
    int incl = x + off;
    if (t < N_SBLK) g_bsum[t] = incl - v;          // exclusive
    if (t == 127) g_rowstart[N_NODES] = incl;      // total = N_EDGES
}

__global__ void scan3_kernel() {            // block exclusive scan + offset
    int i = blockIdx.x * SCAN_BLK + threadIdx.x;
    int v = (i < N_NODES) ? g_deg[i] : 0;
    int lane = threadIdx.x & 31, w = threadIdx.x >> 5;
    int x = v;
#pragma unroll
    for (int o = 1; o < 32; o <<= 1) {
        int y = __shfl_up_sync(0xffffffffu, x, o);
        if (lane >= o) x += y;
    }
    __shared__ int ws[16];
    if (lane == 31) ws[w] = x;
    __syncthreads();
    int woff = 0;
    for (int j = 0; j < w; j++) woff += ws[j];
    int excl = x - v + woff + g_bsum[blockIdx.x];
    if (i < N_NODES) {
        g_rowstart[i] = excl;
        g_cursor[i]   = excl;
    }
}

// ---------------------------------------------------------------------------
// K3: bucket fill — group src ids by dst (order within bucket irrelevant)
// ---------------------------------------------------------------------------
__global__ void fill_kernel(const void* __restrict__ ei) {
    int e = blockIdx.x * blockDim.x + threadIdx.x;
    if (e < N_EDGES) {
        int is32 = g_idx_is32;
        int s = load_idx(ei, e, is32);
        int d = load_idx(ei, (long long)N_EDGES + e, is32);
        int pos = atomicAdd(&g_cursor[d], 1);
        g_esrc[pos] = s;
    }
}

// ---------------------------------------------------------------------------
// K4: bf16-3x tensor GEMM via mma.sync.m16n8k16 (HMMA).
// Stores ONLY g_h16 = fp16(h * dis[row]); out is written by aggregate.
// Also finalizes g_dis = rsqrt(deg+1) and resets g_deg for replay.
// ---------------------------------------------------------------------------
#define APAD      136
#define APADW     68
#define TILE_B    (128 * APAD * 2)
#define SM_DIS    0
#define SM_AHI    512
#define SM_ALO    (SM_AHI + TILE_B)
#define SM_BHI    (SM_ALO + TILE_B)
#define SM_BLO    (SM_BHI + TILE_B)
#define SM_TOTAL  (SM_BLO + TILE_B)  // 139776 bytes

__device__ __forceinline__ void mma16816(float* c, const uint32_t* a,
                                         uint32_t b0, uint32_t b1) {
    asm volatile(
        "mma.sync.aligned.m16n8k16.row.col.f32.bf16.bf16.f32 "
        "{%0,%1,%2,%3}, {%4,%5,%6,%7}, {%8,%9}, {%0,%1,%2,%3};"
        : "+f"(c[0]), "+f"(c[1]), "+f"(c[2]), "+f"(c[3])
        : "r"(a[0]), "r"(a[1]), "r"(a[2]), "r"(a[3]), "r"(b0), "r"(b1));
}

__device__ __forceinline__ uint32_t pack_hi2(float x, float y) {
    __nv_bfloat162 t = make_bfloat162(__float2bfloat16_rn(x), __float2bfloat16_rn(y));
    return *(uint32_t*)&t;
}
__device__ __forceinline__ uint32_t pack_lo2(float x, float y) {
    float hx = __bfloat162float(__float2bfloat16_rn(x));
    float hy = __bfloat162float(__float2bfloat16_rn(y));
    __nv_bfloat162 t = make_bfloat162(__float2bfloat16_rn(x - hx),
                                      __float2bfloat16_rn(y - hy));
    return *(uint32_t*)&t;
}

__global__ void __launch_bounds__(256, 1)
gemm_kernel(const float* __restrict__ x,
            const float* __restrict__ W) {
    extern __shared__ char smem[];
    float*    ep_dis = (float*)(smem + SM_DIS);
    uint32_t* AsHi = (uint32_t*)(smem + SM_AHI);
    uint32_t* AsLo = (uint32_t*)(smem + SM_ALO);
    uint32_t* BsHi = (uint32_t*)(smem + SM_BHI);
    uint32_t* BsLo = (uint32_t*)(smem + SM_BLO);

    const int tid  = threadIdx.x;
    const int wid  = tid >> 5;
    const int lane = tid & 31;
    const int row0 = blockIdx.x * 128;

    // --- Degree finalize for this block's rows ---
    if (tid < 128) {
        int gr = row0 + tid;
        float dis = 0.0f;
        if (gr < N_NODES) {
            int deg = g_deg[gr];
            dis = rsqrtf((float)(deg + 1));
            g_dis[gr] = dis;
            g_deg[gr] = 0;           // reset for next graph replay
        }
        ep_dis[tid] = dis;
    }

    // --- A tile: x[row0..row0+128) -> hi/lo bf16 ---
    for (int i = tid; i < 128 * 32; i += 256) {
        int r  = i >> 5;
        int c4 = (i & 31) << 2;
        int gr = row0 + r;
        float4 v = make_float4(0.f, 0.f, 0.f, 0.f);
        if (gr < N_NODES) v = *(const float4*)(x + (size_t)gr * D + c4);
        uint32_t* dh = AsHi + r * APADW + (c4 >> 1);
        uint32_t* dl = AsLo + r * APADW + (c4 >> 1);
        dh[0] = pack_hi2(v.x, v.y);
        dh[1] = pack_hi2(v.z, v.w);
        dl[0] = pack_lo2(v.x, v.y);
        dl[1] = pack_lo2(v.z, v.w);
    }

    // --- B tile: W^T (n-major rows, k contiguous) hi/lo bf16 ---
    for (int i = tid; i < 128 * 64; i += 256) {
        int k  = i >> 6;
        int n2 = (i & 63) << 1;
        float2 v = *(const float2*)(W + k * D + n2);
        __nv_bfloat16* bh = (__nv_bfloat16*)(smem + SM_BHI);
        __nv_bfloat16* bl = (__nv_bfloat16*)(smem + SM_BLO);
        float h0f = __bfloat162float(__float2bfloat16_rn(v.x));
        float h1f = __bfloat162float(__float2bfloat16_rn(v.y));
        bh[(n2 + 0) * APAD + k] = __float2bfloat16_rn(v.x);
        bh[(n2 + 1) * APAD + k] = __float2bfloat16_rn(v.y);
        bl[(n2 + 0) * APAD + k] = __float2bfloat16_rn(v.x - h0f);
        bl[(n2 + 1) * APAD + k] = __float2bfloat16_rn(v.y - h1f);
    }
    __syncthreads();

    // --- MMA mainloop ---
    const int g = lane >> 2;
    const int t = lane & 3;
    const int wrow = wid * 16;

    float acc[16][4];
#pragma unroll
    for (int nt = 0; nt < 16; nt++)
#pragma unroll
        for (int j = 0; j < 4; j++) acc[nt][j] = 0.0f;

#pragma unroll
    for (int ks = 0; ks < 8; ks++) {
        const int kw = ks * 8 + t;
        uint32_t ahi[4], alo[4];
        ahi[0] = AsHi[(wrow + g)     * APADW + kw];
        ahi[1] = AsHi[(wrow + g + 8) * APADW + kw];
        ahi[2] = AsHi[(wrow + g)     * APADW + kw + 4];
        ahi[3] = AsHi[(wrow + g + 8) * APADW + kw + 4];
        alo[0] = AsLo[(wrow + g)     * APADW + kw];
        alo[1] = AsLo[(wrow + g + 8) * APADW + kw];
        alo[2] = AsLo[(wrow + g)     * APADW + kw + 4];
        alo[3] = AsLo[(wrow + g + 8) * APADW + kw + 4];
#pragma unroll
        for (int nt = 0; nt < 16; nt++) {
            const int brow = (nt * 8 + g) * APADW + kw;
            uint32_t bh0 = BsHi[brow], bh1 = BsHi[brow + 4];
            uint32_t bl0 = BsLo[brow], bl1 = BsLo[brow + 4];
            mma16816(acc[nt], ahi, bh0, bh1);
            mma16816(acc[nt], ahi, bl0, bl1);
            mma16816(acc[nt], alo, bh0, bh1);
        }
    }

    // --- Epilogue: g_h16 = fp16(h * dis[row]) only ---
    const int r0 = row0 + wrow + g;
    const int r1 = r0 + 8;
    const float d0 = ep_dis[wrow + g];
    const float d1 = ep_dis[wrow + g + 8];
    const bool ok0 = (r0 < N_NODES), ok1 = (r1 < N_NODES);
#pragma unroll
    for (int nt = 0; nt < 16; nt++) {
        const int c = nt * 8 + 2 * t;
        if (ok0) {
            float2 hv = make_float2(acc[nt][0] * d0, acc[nt][1] * d0);
            *(__half2*)(g_h16 + (size_t)r0 * D + c) = __float22half2_rn(hv);
        }
        if (ok1) {
            float2 hv = make_float2(acc[nt][2] * d1, acc[nt][3] * d1);
            *(__half2*)(g_h16 + (size_t)r1 * D + c) = __float22half2_rn(hv);
        }
    }
}

// ---------------------------------------------------------------------------
// K5: pull aggregation. One warp per dst node; lane l owns cols [4l, 4l+4).
// out[d] = b + dis[d] * (h~[d] + sum_{s in N(d)} h~[s])   -- no atomics.
// Src ids loaded cooperatively (1 LDG per 32 edges, shfl broadcast).
// ---------------------------------------------------------------------------
__global__ void __launch_bounds__(256)
agg_kernel(const float* __restrict__ bias, float* __restrict__ out) {
    int node = blockIdx.x * 8 + (threadIdx.x >> 5);
    int lane = threadIdx.x & 31;
    if (node >= N_NODES) return;

    const int rs = g_rowstart[node];
    const int re = g_rowstart[node + 1];

    // self-loop seed
    uint2 u = ((const uint2*)(g_h16 + (size_t)node * D))[lane];
    float2 a0 = __half22float2(*(__half2*)&u.x);
    float2 a1 = __half22float2(*(__half2*)&u.y);
    float acc0 = a0.x, acc1 = a0.y, acc2 = a1.x, acc3 = a1.y;

    for (int base = rs; base < re; base += 32) {
        int n = re - base;                       // edges in this batch (<=32)
        int sv = (lane < n) ? g_esrc[base + lane] : 0;
#pragma unroll 4
        for (int j = 0; j < 32; j++) {
            if (j >= n) break;
            int s = __shfl_sync(0xffffffffu, sv, j);
            uint2 v = ((const uint2*)(g_h16 + (size_t)s * D))[lane];
            float2 b0 = __half22float2(*(__half2*)&v.x);
            float2 b1 = __half22float2(*(__half2*)&v.y);
            acc0 += b0.x; acc1 += b0.y; acc2 += b1.x; acc3 += b1.y;
        }
    }

    const float dd = g_dis[node];
    float4 bv = *(const float4*)(bias + lane * 4);
    float4 ov;
    ov.x = bv.x + dd * acc0;
    ov.y = bv.y + dd * acc1;
    ov.z = bv.z + dd * acc2;
    ov.w = bv.w + dd * acc3;
    *(float4*)(out + (size_t)node * D + lane * 4) = ov;
}

// ---------------------------------------------------------------------------
// Launch: 7 kernels
// ---------------------------------------------------------------------------
extern "C" void kernel_launch(void* const* d_in, const int* in_sizes, int n_in,
                              void* d_out, int out_size) {
    const float* x  = (const float*)d_in[0];
    const void*  ei = d_in[1];
    const float* W  = (const float*)d_in[2];
    const float* b  = (const float*)d_in[3];
    float*       out = (float*)d_out;

    deg_count_kernel<<<(N_EDGES + 511) / 512, 256>>>(ei);

    scan1_kernel<<<N_SBLK, SCAN_BLK>>>();
    scan2_kernel<<<1, 128>>>();
    scan3_kernel<<<N_SBLK, SCAN_BLK>>>();

    fill_kernel<<<(N_EDGES + 255) / 256, 256>>>(ei);

    cudaFuncSetAttribute(gemm_kernel,
                         cudaFuncAttributeMaxDynamicSharedMemorySize, SM_TOTAL);
    gemm_kernel<<<(N_NODES + 127) / 128, 256, SM_TOTAL>>>(x, W);

    agg_kernel<<<(N_NODES + 7) / 8, 256>>>(b, out);
}